// round 14
// baseline (speedup 1.0000x reference)
#include <cuda_runtime.h>
#include <cuda_bf16.h>
#include <cstdint>

#define NB 1024
#define NM 8192
#define NN 32
#define NS 128
#define MSPLIT 16
#define NCHUNK 16
#define NGRP 256
#define NEG_PI_LN2 (-4.532360141827194f)
#define QCLAMP (-113.3090035456798f)

// smem: A2/z region (A2 [128][144B] = 18432; z staged first as [128][80B]) + 2 buffers
#define SM_A2Z 0
#define SM_BUF 18432
#define BUF_SZ 14592       // W 4608 | B 9216 | P0 512 | P1 256
#define BO_W   0           // [32][72] bf16 stride 144B
#define BO_B   4608        // [64][72] bf16 stride 144B
#define BO_P0  13824
#define BO_P1  14336
#define SM_TOT (SM_BUF + 2 * BUF_SZ)   // 47616 (< 48KB static)

__device__ __nv_bfloat16 g_zt[8 * 128 * 32];
__device__ float         g_zn[NB];
__device__ __nv_bfloat16 g_WB[NGRP * 32 * 64];   // [32 k][64 n] (n: 0-31 zj, 32-63 bhat)
__device__ __nv_bfloat16 g_TB[NGRP * 64 * 128];  // [64 k][128 s] (k: 0-31 th, 32-63 tl)
__device__ float4        g_par0[NM];             // pre-scaled by -pi/ln2
__device__ float2        g_par1[NM];             // {c, alpha}
__device__ float         g_part[(size_t)MSPLIT * NB * NS];

__device__ __forceinline__ uint32_t smem_u32(const void* p) {
    uint32_t a;
    asm("{ .reg .u64 t; cvta.to.shared.u64 t, %1; cvt.u32.u64 %0, t; }" : "=r"(a) : "l"(p));
    return a;
}
__device__ __forceinline__ void ldsm4(uint32_t* r, uint32_t a) {
    asm volatile("ldmatrix.sync.aligned.m8n8.x4.shared.b16 {%0,%1,%2,%3}, [%4];"
        : "=r"(r[0]), "=r"(r[1]), "=r"(r[2]), "=r"(r[3]) : "r"(a));
}
__device__ __forceinline__ void ldsm4t(uint32_t* r, uint32_t a) {
    asm volatile("ldmatrix.sync.aligned.m8n8.x4.trans.shared.b16 {%0,%1,%2,%3}, [%4];"
        : "=r"(r[0]), "=r"(r[1]), "=r"(r[2]), "=r"(r[3]) : "r"(a));
}
__device__ __forceinline__ void mmabf(float* c, const uint32_t* a, uint32_t b0, uint32_t b1) {
    asm volatile("mma.sync.aligned.m16n8k16.row.col.f32.bf16.bf16.f32 "
        "{%0,%1,%2,%3}, {%4,%5,%6,%7}, {%8,%9}, {%0,%1,%2,%3};"
        : "+f"(c[0]), "+f"(c[1]), "+f"(c[2]), "+f"(c[3])
        : "r"(a[0]), "r"(a[1]), "r"(a[2]), "r"(a[3]), "r"(b0), "r"(b1));
}
__device__ __forceinline__ uint32_t lmaddr(uint32_t base, int rowB, int colB, int strideB,
                                           int mat, int lr) {
    return base + (uint32_t)((rowB + lr + 8 * (mat & 1)) * strideB + (colB + 8 * (mat >> 1)) * 2);
}
__device__ __forceinline__ uint32_t pk(__nv_bfloat16 a, __nv_bfloat16 b) {
    __nv_bfloat162 t; t.x = a; t.y = b;
    return *reinterpret_cast<uint32_t*>(&t);
}
__device__ __forceinline__ float ex2f(float x) {
    float r; asm("ex2.approx.f32 %0, %1;" : "=f"(r) : "f"(x)); return r;
}
#define CPA16(d, s) asm volatile("cp.async.cg.shared.global [%0], [%1], 16;" :: "r"(d), "l"(s) : "memory")
#define CPA8(d, s)  asm volatile("cp.async.ca.shared.global [%0], [%1], 8;"  :: "r"(d), "l"(s) : "memory")
#define CPCOMMIT()  asm volatile("cp.async.commit_group;" ::: "memory")
#define CPWAIT0()   asm volatile("cp.async.wait_group 0;" ::: "memory")
#define BARS(id, n) asm volatile("bar.sync %0, %1;" :: "r"(id), "r"(n) : "memory")
#define BARA(id, n) asm volatile("bar.arrive %0, %1;" :: "r"(id), "r"(n) : "memory")

// ---------------- prep kernels ----------------
__global__ void prep_z_kernel(const float* __restrict__ z) {
    int b = blockIdx.x * blockDim.x + threadIdx.x;
    if (b >= NB) return;
    const float4* z4 = reinterpret_cast<const float4*>(z + b * NN);
    float s = 0.f;
    __nv_bfloat16* dst = g_zt + (b >> 7) * 4096 + (b & 127) * 32;
    #pragma unroll
    for (int i = 0; i < 8; i++) {
        float4 v = z4[i];
        s = fmaf(v.x, v.x, fmaf(v.y, v.y, fmaf(v.z, v.z, fmaf(v.w, v.w, s))));
        reinterpret_cast<uint2*>(dst)[i] =
            make_uint2(pk(__float2bfloat16(v.x), __float2bfloat16(v.y)),
                       pk(__float2bfloat16(v.z), __float2bfloat16(v.w)));
    }
    g_zn[b] = s;
}

__global__ void prep_m_kernel(const float* __restrict__ zj, const float* __restrict__ vd,
                              const float* __restrict__ alpha, const float* __restrict__ sp,
                              const float* __restrict__ spr, const float* __restrict__ that) {
    __shared__ float zs[32][33], ds[32][33], invs[32];
    int grp = blockIdx.x, tid = threadIdx.x;
    {
        int mm = tid >> 3, part = tid & 7;
        float4 a = reinterpret_cast<const float4*>(zj + (size_t)(grp * 32 + mm) * NN)[part];
        float4 b = reinterpret_cast<const float4*>(vd + (size_t)(grp * 32 + mm) * NN)[part];
        zs[mm][part*4] = a.x; zs[mm][part*4+1] = a.y; zs[mm][part*4+2] = a.z; zs[mm][part*4+3] = a.w;
        ds[mm][part*4] = b.x; ds[mm][part*4+1] = b.y; ds[mm][part*4+2] = b.z; ds[mm][part*4+3] = b.w;
    }
    {   // T_hat hi/lo split
        int m = tid >> 3, s0 = (tid & 7) * 16;
        const float4* src = reinterpret_cast<const float4*>(that + (size_t)(grp * 32 + m) * NS + s0);
        __nv_bfloat16* th = g_TB + (size_t)grp * 8192 + m * 128 + s0;
        __nv_bfloat16* tl = th + 32 * 128;
        #pragma unroll
        for (int i = 0; i < 4; i++) {
            float4 v = src[i];
            float f[4] = {v.x, v.y, v.z, v.w};
            #pragma unroll
            for (int j = 0; j < 4; j++) {
                __nv_bfloat16 h = __float2bfloat16(f[j]);
                th[i * 4 + j] = h;
                tl[i * 4 + j] = __float2bfloat16(f[j] - __bfloat162float(h));
            }
        }
    }
    __syncthreads();
    if (tid < 32) {
        int m = grp * 32 + tid;
        float d2 = 0.f, zz = 0.f, cr = 0.f;
        #pragma unroll
        for (int k = 0; k < 32; k++) {
            float dv = ds[tid][k], zv = zs[tid][k];
            d2 = fmaf(dv, dv, d2); zz = fmaf(zv, zv, zz); cr = fmaf(zv, dv, cr);
        }
        float dn = sqrtf(d2);
        float inv = (dn > 1e-6f) ? (1.0f / dn) : 0.0f;
        invs[tid] = inv;
        const float tiny = 1.1920929e-7f;
        float a = fmaxf(sp[m], tiny), bb = fmaxf(spr[m], tiny);
        float wpar = 1.f / (a * a), wperp = 1.f / (bb * bb);
        // pre-scaled by -pi/ln2: gain = alpha * ex2(q'')
        g_par0[m] = make_float4(NEG_PI_LN2 * wperp, NEG_PI_LN2 * wperp * zz,
                                NEG_PI_LN2 * -2.f * wperp, NEG_PI_LN2 * (wpar - wperp));
        g_par1[m] = make_float2(cr * inv, alpha[m]);
    }
    __syncthreads();
    int k = tid >> 3, c8 = (tid & 7) * 8;
    uint32_t o[4];
    #pragma unroll
    for (int j = 0; j < 4; j++) {
        int n0 = c8 + 2 * j, n1 = n0 + 1;
        float v0 = (n0 < 32) ? zs[n0][k] : ds[n0 - 32][k] * invs[n0 - 32];
        float v1 = (n1 < 32) ? zs[n1][k] : ds[n1 - 32][k] * invs[n1 - 32];
        o[j] = pk(__float2bfloat16(v0), __float2bfloat16(v1));
    }
    reinterpret_cast<uint4*>(g_WB + grp * 2048 + k * 64 + c8)[0] = make_uint4(o[0], o[1], o[2], o[3]);
}

// ---------------- warp-specialized fused kernel ----------------
__global__ void __launch_bounds__(256, 2) fused_kernel() {
    __shared__ __align__(16) char smc[SM_TOT];
    const uint32_t sb = smem_u32(smc);
    const int tid = threadIdx.x, lane = tid & 31;
    const int g = lane >> 2, t = lane & 3;
    const int mat = lane >> 3, lr = lane & 7;
    const int bb = blockIdx.x, ms = blockIdx.y, sh = blockIdx.z;

    if (tid < 128) {
        // ================= PRODUCER warps 0-3: gains =================
        const int ptid = tid, pw = tid >> 5;
        // initial prefetch W/par(0)
        {
            const int grp = ms * NCHUNK;
            uint32_t nd = sb + SM_BUF;
            #pragma unroll
            for (int i = 0; i < 2; i++) {
                int o = ptid + i * 128, r = o >> 3, c = o & 7;
                CPA16(nd + BO_W + r * 144 + c * 16, g_WB + grp * 2048 + r * 64 + c * 8);
            }
            if (ptid < 32)      CPA16(nd + BO_P0 + ptid * 16, g_par0 + grp * 32 + ptid);
            else if (ptid < 64) CPA8(nd + BO_P1 + (ptid - 32) * 8, g_par1 + grp * 32 + ptid - 32);
            CPCOMMIT();
        }
        // stage z into A2 region ([128][80B]) and extract A-frags
        {
            const uint4* zs = reinterpret_cast<const uint4*>(g_zt) + bb * 512;
            #pragma unroll
            for (int i = 0; i < 4; i++) {
                int o = ptid + i * 128, r = o >> 2, c = o & 3;
                *reinterpret_cast<uint4*>(smc + SM_A2Z + r * 80 + c * 16) = zs[o];
            }
        }
        BARS(5, 128);
        uint32_t az[2][2][4];
        float zn[2][2];
        #pragma unroll
        for (int rg = 0; rg < 2; rg++) {
            #pragma unroll
            for (int kt = 0; kt < 2; kt++)
                ldsm4(az[rg][kt], lmaddr(sb + SM_A2Z, pw * 32 + rg * 16, kt * 16, 80, mat, lr));
            zn[rg][0] = g_zn[bb * 128 + pw * 32 + rg * 16 + g];
            zn[rg][1] = g_zn[bb * 128 + pw * 32 + rg * 16 + g + 8];
        }
        BARS(5, 128);   // all az extracted before A2 region is overwritten

        for (int ch = 0; ch < NCHUNK; ch++) {
            const uint32_t bd = sb + SM_BUF + (ch & 1) * BUF_SZ;
            CPWAIT0();
            BARS(5, 128);                     // whole buffer(ch) landed; buf(ch-1) reads done
            if (ch + 1 < NCHUNK) {
                const int grp = ms * NCHUNK + ch + 1;
                uint32_t nd = sb + SM_BUF + ((ch + 1) & 1) * BUF_SZ;
                #pragma unroll
                for (int i = 0; i < 2; i++) {
                    int o = ptid + i * 128, r = o >> 3, c = o & 7;
                    CPA16(nd + BO_W + r * 144 + c * 16, g_WB + grp * 2048 + r * 64 + c * 8);
                }
                if (ptid < 32)      CPA16(nd + BO_P0 + ptid * 16, g_par0 + grp * 32 + ptid);
                else if (ptid < 64) CPA8(nd + BO_P1 + (ptid - 32) * 8, g_par1 + grp * 32 + ptid - 32);
                CPCOMMIT();
            }
            uint32_t wf[8][4];
            #pragma unroll
            for (int kt = 0; kt < 2; kt++)
                #pragma unroll
                for (int nt2 = 0; nt2 < 4; nt2++)
                    ldsm4t(wf[kt * 4 + nt2], lmaddr(bd + BO_W, kt * 16, nt2 * 16, 144, mat, lr));

            #pragma unroll
            for (int rg = 0; rg < 2; rg++) {
                float c1[32];
                #pragma unroll
                for (int i = 0; i < 32; i++) c1[i] = 0.f;
                #pragma unroll
                for (int kt = 0; kt < 2; kt++)
                    #pragma unroll
                    for (int nt2 = 0; nt2 < 4; nt2++) {
                        mmabf(c1 + nt2 * 8,     az[rg][kt], wf[kt*4+nt2][0], wf[kt*4+nt2][1]);
                        mmabf(c1 + nt2 * 8 + 4, az[rg][kt], wf[kt*4+nt2][2], wf[kt*4+nt2][3]);
                    }
                if (rg == 0 && ch > 0) BARS(2, 256);   // A2(ch-1) consumed by all consumers
                const int rowA = pw * 32 + rg * 16 + g;
                #pragma unroll
                for (int j = 0; j < 4; j++) {
                    const int m0p = 8 * j + 2 * t;
                    float4 pA = *reinterpret_cast<float4*>(smc + (bd - sb) + BO_P0 + m0p * 16);
                    float4 pB = *reinterpret_cast<float4*>(smc + (bd - sb) + BO_P0 + (m0p + 1) * 16);
                    float2 cA = *reinterpret_cast<float2*>(smc + (bd - sb) + BO_P1 + m0p * 8);
                    float2 cB = *reinterpret_cast<float2*>(smc + (bd - sb) + BO_P1 + (m0p + 1) * 8);
                    float gn[4];
                    #pragma unroll
                    for (int i = 0; i < 4; i++) {
                        float u = c1[4 * j + i];
                        float v = c1[(j + 4) * 4 + i];
                        float znv = zn[rg][i >> 1];
                        float4 pp = (i & 1) ? pB : pA;
                        float2 cc = (i & 1) ? cB : cA;
                        float tq = v - cc.x;
                        float q = fmaf(pp.x, znv, pp.y);
                        q = fmaf(pp.z, u, q);
                        q = fmaf(pp.w * tq, tq, q);
                        q = fmaxf(q, QCLAMP);
                        gn[i] = cc.y * ex2f(q);
                    }
                    __nv_bfloat16 h0 = __float2bfloat16(gn[0]), h1 = __float2bfloat16(gn[1]);
                    __nv_bfloat16 h2 = __float2bfloat16(gn[2]), h3 = __float2bfloat16(gn[3]);
                    char* r0 = smc + SM_A2Z + rowA * 144;
                    char* r1 = smc + SM_A2Z + (rowA + 8) * 144;
                    *reinterpret_cast<uint32_t*>(r0 + m0p * 2) = pk(h0, h1);
                    *reinterpret_cast<uint32_t*>(r1 + m0p * 2) = pk(h2, h3);
                    *reinterpret_cast<uint32_t*>(r0 + (32 + m0p) * 2) =
                        pk(__float2bfloat16(gn[0] - __bfloat162float(h0)),
                           __float2bfloat16(gn[1] - __bfloat162float(h1)));
                    *reinterpret_cast<uint32_t*>(r1 + (32 + m0p) * 2) =
                        pk(__float2bfloat16(gn[2] - __bfloat162float(h2)),
                           __float2bfloat16(gn[3] - __bfloat162float(h3)));
                }
            }
            __threadfence_block();
            BARA(1, 256);                      // gains(ch) ready
        }
    } else {
        // ================= CONSUMER warps 4-7: output GEMM =================
        const int ctid = tid - 128, cw = ctid >> 5;
        float acc[64];
        #pragma unroll
        for (int i = 0; i < 64; i++) acc[i] = 0.f;
        {   // initial prefetch B(0)
            const int grp = ms * NCHUNK;
            uint32_t nd = sb + SM_BUF;
            #pragma unroll
            for (int i = 0; i < 4; i++) {
                int o = ctid + i * 128, r = o >> 3, c = o & 7;
                CPA16(nd + BO_B + r * 144 + c * 16,
                      g_TB + (size_t)grp * 8192 + sh * 64 + r * 128 + c * 8);
            }
            CPCOMMIT();
        }
        for (int ch = 0; ch < NCHUNK; ch++) {
            const uint32_t bd = sb + SM_BUF + (ch & 1) * BUF_SZ;
            CPWAIT0();
            BARS(4, 128);                     // B(ch) landed; B(ch-1) reads done
            if (ch + 1 < NCHUNK) {
                const int grp = ms * NCHUNK + ch + 1;
                uint32_t nd = sb + SM_BUF + ((ch + 1) & 1) * BUF_SZ;
                #pragma unroll
                for (int i = 0; i < 4; i++) {
                    int o = ctid + i * 128, r = o >> 3, c = o & 7;
                    CPA16(nd + BO_B + r * 144 + c * 16,
                          g_TB + (size_t)grp * 8192 + sh * 64 + r * 128 + c * 8);
                }
                CPCOMMIT();
            }
            BARS(1, 256);                     // gains(ch) ready
            uint32_t af[2][4][4];
            #pragma unroll
            for (int rg = 0; rg < 2; rg++)
                #pragma unroll
                for (int kt = 0; kt < 4; kt++)
                    ldsm4(af[rg][kt], lmaddr(sb + SM_A2Z, cw * 32 + rg * 16, kt * 16, 144, mat, lr));
            BARA(2, 256);                     // gains(ch) consumed
            #pragma unroll
            for (int nt2 = 0; nt2 < 4; nt2++) {
                uint32_t bf[4][4];
                #pragma unroll
                for (int kt = 0; kt < 4; kt++)
                    ldsm4t(bf[kt], lmaddr(bd + BO_B, kt * 16, nt2 * 16, 144, mat, lr));
                #pragma unroll
                for (int rg = 0; rg < 2; rg++) {
                    float* a = acc + rg * 32 + nt2 * 8;
                    mmabf(a,     af[rg][0], bf[0][0], bf[0][1]);   // gh0*th0
                    mmabf(a + 4, af[rg][0], bf[0][2], bf[0][3]);
                    mmabf(a,     af[rg][2], bf[0][0], bf[0][1]);   // gl0*th0
                    mmabf(a + 4, af[rg][2], bf[0][2], bf[0][3]);
                    mmabf(a,     af[rg][1], bf[1][0], bf[1][1]);   // gh1*th1
                    mmabf(a + 4, af[rg][1], bf[1][2], bf[1][3]);
                    mmabf(a,     af[rg][3], bf[1][0], bf[1][1]);   // gl1*th1
                    mmabf(a + 4, af[rg][3], bf[1][2], bf[1][3]);
                    mmabf(a,     af[rg][0], bf[2][0], bf[2][1]);   // gh0*tl0
                    mmabf(a + 4, af[rg][0], bf[2][2], bf[2][3]);
                    mmabf(a,     af[rg][1], bf[3][0], bf[3][1]);   // gh1*tl1
                    mmabf(a + 4, af[rg][1], bf[3][2], bf[3][3]);
                }
            }
        }
        // write partials
        float* op = g_part + ((size_t)ms * NB + bb * 128 + cw * 32) * NS + sh * 64;
        #pragma unroll
        for (int rg = 0; rg < 2; rg++)
            #pragma unroll
            for (int nt2 = 0; nt2 < 4; nt2++)
                #pragma unroll
                for (int h = 0; h < 2; h++) {
                    const float* a = acc + rg * 32 + nt2 * 8 + h * 4;
                    int col = nt2 * 16 + h * 8 + 2 * t;
                    *reinterpret_cast<float2*>(op + (rg * 16 + g) * NS + col) =
                        make_float2(a[0], a[1]);
                    *reinterpret_cast<float2*>(op + (rg * 16 + g + 8) * NS + col) =
                        make_float2(a[2], a[3]);
                }
    }
}

__global__ void reduce_kernel(float* __restrict__ out) {
    int idx = blockIdx.x * blockDim.x + threadIdx.x;   // B*S/2 threads
    const float2* gp = reinterpret_cast<const float2*>(g_part);
    const size_t stride = (size_t)NB * NS / 2;
    float2 a0 = {0,0}, a1 = {0,0}, a2 = {0,0}, a3 = {0,0};
    #pragma unroll
    for (int p = 0; p < 4; p++) {
        float2 v0 = gp[(4 * p + 0) * stride + idx];
        float2 v1 = gp[(4 * p + 1) * stride + idx];
        float2 v2 = gp[(4 * p + 2) * stride + idx];
        float2 v3 = gp[(4 * p + 3) * stride + idx];
        a0.x += v0.x; a0.y += v0.y;  a1.x += v1.x; a1.y += v1.y;
        a2.x += v2.x; a2.y += v2.y;  a3.x += v3.x; a3.y += v3.y;
    }
    a0.x += a1.x + a2.x + a3.x;
    a0.y += a1.y + a2.y + a3.y;
    reinterpret_cast<float2*>(out)[idx] = a0;
}

extern "C" void kernel_launch(void* const* d_in, const int* in_sizes, int n_in,
                              void* d_out, int out_size) {
    const float* z     = (const float*)d_in[0];
    const float* zj    = (const float*)d_in[1];
    const float* vd    = (const float*)d_in[2];
    const float* that  = (const float*)d_in[3];
    const float* alpha = (const float*)d_in[4];
    const float* sp    = (const float*)d_in[5];
    const float* spr   = (const float*)d_in[6];
    float* out = (float*)d_out;

    prep_z_kernel<<<4, 256>>>(z);
    prep_m_kernel<<<NGRP, 256>>>(zj, vd, alpha, sp, spr, that);
    fused_kernel<<<dim3(NB / 128, MSPLIT, 2), 256>>>();
    reduce_kernel<<<512, 128>>>(out);
}

// round 15
// speedup vs baseline: 1.0120x; 1.0120x over previous
#include <cuda_runtime.h>
#include <cuda_bf16.h>
#include <cstdint>

#define NB 1024
#define NM 8192
#define NN 32
#define NS 128
#define MSPLIT 16
#define NCHUNK 16
#define NGRP 256
#define NEG_PI_LN2 (-4.532360141827194f)
#define QCLAMP (-113.3090035456798f)

// smem: A2/z region (A2 [128][144B] = 18432; z staged first as [128][80B]) + 2 buffers
#define SM_A2Z 0
#define SM_BUF 18432
#define BUF_SZ 14592       // W 4608 | B 9216 | P0 512 | P1 256
#define BO_W   0           // [32][72] bf16 stride 144B
#define BO_B   4608        // [64][72] bf16 stride 144B
#define BO_P0  13824
#define BO_P1  14336
#define SM_TOT (SM_BUF + 2 * BUF_SZ)   // 47616 (< 48KB static)

__device__ __nv_bfloat16 g_zt[8 * 128 * 32];
__device__ float         g_zn[NB];
__device__ __nv_bfloat16 g_WB[NGRP * 32 * 64];   // [32 k][64 n] (n: 0-31 zj, 32-63 bhat)
__device__ __nv_bfloat16 g_TB[NGRP * 64 * 128];  // [64 k][128 s] (k: 0-31 th, 32-63 tl)
__device__ float4        g_par0[NM];             // pre-scaled by -pi/ln2
__device__ float2        g_par1[NM];             // {c, alpha}
__device__ float         g_part[(size_t)MSPLIT * NB * NS];

__device__ __forceinline__ uint32_t smem_u32(const void* p) {
    uint32_t a;
    asm("{ .reg .u64 t; cvta.to.shared.u64 t, %1; cvt.u32.u64 %0, t; }" : "=r"(a) : "l"(p));
    return a;
}
__device__ __forceinline__ void ldsm4(uint32_t* r, uint32_t a) {
    asm volatile("ldmatrix.sync.aligned.m8n8.x4.shared.b16 {%0,%1,%2,%3}, [%4];"
        : "=r"(r[0]), "=r"(r[1]), "=r"(r[2]), "=r"(r[3]) : "r"(a));
}
__device__ __forceinline__ void ldsm4t(uint32_t* r, uint32_t a) {
    asm volatile("ldmatrix.sync.aligned.m8n8.x4.trans.shared.b16 {%0,%1,%2,%3}, [%4];"
        : "=r"(r[0]), "=r"(r[1]), "=r"(r[2]), "=r"(r[3]) : "r"(a));
}
__device__ __forceinline__ void mmabf(float* c, const uint32_t* a, uint32_t b0, uint32_t b1) {
    asm volatile("mma.sync.aligned.m16n8k16.row.col.f32.bf16.bf16.f32 "
        "{%0,%1,%2,%3}, {%4,%5,%6,%7}, {%8,%9}, {%0,%1,%2,%3};"
        : "+f"(c[0]), "+f"(c[1]), "+f"(c[2]), "+f"(c[3])
        : "r"(a[0]), "r"(a[1]), "r"(a[2]), "r"(a[3]), "r"(b0), "r"(b1));
}
__device__ __forceinline__ uint32_t lmaddr(uint32_t base, int rowB, int colB, int strideB,
                                           int mat, int lr) {
    return base + (uint32_t)((rowB + lr + 8 * (mat & 1)) * strideB + (colB + 8 * (mat >> 1)) * 2);
}
__device__ __forceinline__ uint32_t pk(__nv_bfloat16 a, __nv_bfloat16 b) {
    __nv_bfloat162 t; t.x = a; t.y = b;
    return *reinterpret_cast<uint32_t*>(&t);
}
__device__ __forceinline__ float ex2f(float x) {
    float r; asm("ex2.approx.f32 %0, %1;" : "=f"(r) : "f"(x)); return r;
}
#define CPA16(d, s) asm volatile("cp.async.cg.shared.global [%0], [%1], 16;" :: "r"(d), "l"(s) : "memory")
#define CPA8(d, s)  asm volatile("cp.async.ca.shared.global [%0], [%1], 8;"  :: "r"(d), "l"(s) : "memory")
#define CPCOMMIT()  asm volatile("cp.async.commit_group;" ::: "memory")
#define CPWAIT0()   asm volatile("cp.async.wait_group 0;" ::: "memory")
#define BARS(id, n) asm volatile("bar.sync %0, %1;" :: "r"(id), "r"(n) : "memory")
#define BARA(id, n) asm volatile("bar.arrive %0, %1;" :: "r"(id), "r"(n) : "memory")

// ---------------- prep kernels ----------------
__global__ void prep_z_kernel(const float* __restrict__ z) {
    int b = blockIdx.x * blockDim.x + threadIdx.x;
    if (b >= NB) return;
    const float4* z4 = reinterpret_cast<const float4*>(z + b * NN);
    float s = 0.f;
    __nv_bfloat16* dst = g_zt + (b >> 7) * 4096 + (b & 127) * 32;
    #pragma unroll
    for (int i = 0; i < 8; i++) {
        float4 v = z4[i];
        s = fmaf(v.x, v.x, fmaf(v.y, v.y, fmaf(v.z, v.z, fmaf(v.w, v.w, s))));
        reinterpret_cast<uint2*>(dst)[i] =
            make_uint2(pk(__float2bfloat16(v.x), __float2bfloat16(v.y)),
                       pk(__float2bfloat16(v.z), __float2bfloat16(v.w)));
    }
    g_zn[b] = s;
}

__global__ void prep_m_kernel(const float* __restrict__ zj, const float* __restrict__ vd,
                              const float* __restrict__ alpha, const float* __restrict__ sp,
                              const float* __restrict__ spr, const float* __restrict__ that) {
    __shared__ float zs[32][33], ds[32][33], invs[32];
    int grp = blockIdx.x, tid = threadIdx.x;
    {
        int mm = tid >> 3, part = tid & 7;
        float4 a = reinterpret_cast<const float4*>(zj + (size_t)(grp * 32 + mm) * NN)[part];
        float4 b = reinterpret_cast<const float4*>(vd + (size_t)(grp * 32 + mm) * NN)[part];
        zs[mm][part*4] = a.x; zs[mm][part*4+1] = a.y; zs[mm][part*4+2] = a.z; zs[mm][part*4+3] = a.w;
        ds[mm][part*4] = b.x; ds[mm][part*4+1] = b.y; ds[mm][part*4+2] = b.z; ds[mm][part*4+3] = b.w;
    }
    {   // T_hat hi/lo split
        int m = tid >> 3, s0 = (tid & 7) * 16;
        const float4* src = reinterpret_cast<const float4*>(that + (size_t)(grp * 32 + m) * NS + s0);
        __nv_bfloat16* th = g_TB + (size_t)grp * 8192 + m * 128 + s0;
        __nv_bfloat16* tl = th + 32 * 128;
        #pragma unroll
        for (int i = 0; i < 4; i++) {
            float4 v = src[i];
            float f[4] = {v.x, v.y, v.z, v.w};
            #pragma unroll
            for (int j = 0; j < 4; j++) {
                __nv_bfloat16 h = __float2bfloat16(f[j]);
                th[i * 4 + j] = h;
                tl[i * 4 + j] = __float2bfloat16(f[j] - __bfloat162float(h));
            }
        }
    }
    __syncthreads();
    if (tid < 32) {
        int m = grp * 32 + tid;
        float d2 = 0.f, zz = 0.f, cr = 0.f;
        #pragma unroll
        for (int k = 0; k < 32; k++) {
            float dv = ds[tid][k], zv = zs[tid][k];
            d2 = fmaf(dv, dv, d2); zz = fmaf(zv, zv, zz); cr = fmaf(zv, dv, cr);
        }
        float dn = sqrtf(d2);
        float inv = (dn > 1e-6f) ? (1.0f / dn) : 0.0f;
        invs[tid] = inv;
        const float tiny = 1.1920929e-7f;
        float a = fmaxf(sp[m], tiny), bb = fmaxf(spr[m], tiny);
        float wpar = 1.f / (a * a), wperp = 1.f / (bb * bb);
        // pre-scaled by -pi/ln2: gain = alpha * ex2(q'')
        g_par0[m] = make_float4(NEG_PI_LN2 * wperp, NEG_PI_LN2 * wperp * zz,
                                NEG_PI_LN2 * -2.f * wperp, NEG_PI_LN2 * (wpar - wperp));
        g_par1[m] = make_float2(cr * inv, alpha[m]);
    }
    __syncthreads();
    int k = tid >> 3, c8 = (tid & 7) * 8;
    uint32_t o[4];
    #pragma unroll
    for (int j = 0; j < 4; j++) {
        int n0 = c8 + 2 * j, n1 = n0 + 1;
        float v0 = (n0 < 32) ? zs[n0][k] : ds[n0 - 32][k] * invs[n0 - 32];
        float v1 = (n1 < 32) ? zs[n1][k] : ds[n1 - 32][k] * invs[n1 - 32];
        o[j] = pk(__float2bfloat16(v0), __float2bfloat16(v1));
    }
    reinterpret_cast<uint4*>(g_WB + grp * 2048 + k * 64 + c8)[0] = make_uint4(o[0], o[1], o[2], o[3]);
}

// ---------------- warp-specialized fused kernel ----------------
__global__ void __launch_bounds__(256, 2) fused_kernel() {
    __shared__ __align__(16) char smc[SM_TOT];
    const uint32_t sb = smem_u32(smc);
    const int tid = threadIdx.x, lane = tid & 31;
    const int g = lane >> 2, t = lane & 3;
    const int mat = lane >> 3, lr = lane & 7;
    const int bb = blockIdx.x, ms = blockIdx.y, sh = blockIdx.z;

    if (tid < 128) {
        // ================= PRODUCER warps 0-3: gains =================
        const int ptid = tid, pw = tid >> 5;
        // initial prefetch W/par(0)
        {
            const int grp = ms * NCHUNK;
            uint32_t nd = sb + SM_BUF;
            #pragma unroll
            for (int i = 0; i < 2; i++) {
                int o = ptid + i * 128, r = o >> 3, c = o & 7;
                CPA16(nd + BO_W + r * 144 + c * 16, g_WB + grp * 2048 + r * 64 + c * 8);
            }
            if (ptid < 32)      CPA16(nd + BO_P0 + ptid * 16, g_par0 + grp * 32 + ptid);
            else if (ptid < 64) CPA8(nd + BO_P1 + (ptid - 32) * 8, g_par1 + grp * 32 + ptid - 32);
            CPCOMMIT();
        }
        // stage z into A2 region ([128][80B]) and extract A-frags
        {
            const uint4* zs = reinterpret_cast<const uint4*>(g_zt) + bb * 512;
            #pragma unroll
            for (int i = 0; i < 4; i++) {
                int o = ptid + i * 128, r = o >> 2, c = o & 3;
                *reinterpret_cast<uint4*>(smc + SM_A2Z + r * 80 + c * 16) = zs[o];
            }
        }
        BARS(5, 128);
        uint32_t az[2][2][4];
        float zn[2][2];
        #pragma unroll
        for (int rg = 0; rg < 2; rg++) {
            #pragma unroll
            for (int kt = 0; kt < 2; kt++)
                ldsm4(az[rg][kt], lmaddr(sb + SM_A2Z, pw * 32 + rg * 16, kt * 16, 80, mat, lr));
            zn[rg][0] = g_zn[bb * 128 + pw * 32 + rg * 16 + g];
            zn[rg][1] = g_zn[bb * 128 + pw * 32 + rg * 16 + g + 8];
        }
        BARS(5, 128);   // all az extracted before A2 region is overwritten

        for (int ch = 0; ch < NCHUNK; ch++) {
            const uint32_t bd = sb + SM_BUF + (ch & 1) * BUF_SZ;
            CPWAIT0();
            BARS(5, 128);                     // whole buffer(ch) landed; buf(ch-1) reads done
            if (ch + 1 < NCHUNK) {
                const int grp = ms * NCHUNK + ch + 1;
                uint32_t nd = sb + SM_BUF + ((ch + 1) & 1) * BUF_SZ;
                #pragma unroll
                for (int i = 0; i < 2; i++) {
                    int o = ptid + i * 128, r = o >> 3, c = o & 7;
                    CPA16(nd + BO_W + r * 144 + c * 16, g_WB + grp * 2048 + r * 64 + c * 8);
                }
                if (ptid < 32)      CPA16(nd + BO_P0 + ptid * 16, g_par0 + grp * 32 + ptid);
                else if (ptid < 64) CPA8(nd + BO_P1 + (ptid - 32) * 8, g_par1 + grp * 32 + ptid - 32);
                CPCOMMIT();
            }
            uint32_t wf[8][4];
            #pragma unroll
            for (int kt = 0; kt < 2; kt++)
                #pragma unroll
                for (int nt2 = 0; nt2 < 4; nt2++)
                    ldsm4t(wf[kt * 4 + nt2], lmaddr(bd + BO_W, kt * 16, nt2 * 16, 144, mat, lr));

            #pragma unroll
            for (int rg = 0; rg < 2; rg++) {
                float c1[32];
                #pragma unroll
                for (int i = 0; i < 32; i++) c1[i] = 0.f;
                #pragma unroll
                for (int kt = 0; kt < 2; kt++)
                    #pragma unroll
                    for (int nt2 = 0; nt2 < 4; nt2++) {
                        mmabf(c1 + nt2 * 8,     az[rg][kt], wf[kt*4+nt2][0], wf[kt*4+nt2][1]);
                        mmabf(c1 + nt2 * 8 + 4, az[rg][kt], wf[kt*4+nt2][2], wf[kt*4+nt2][3]);
                    }
                if (rg == 0 && ch > 0) BARS(2, 256);   // A2(ch-1) consumed by all consumers
                const int rowA = pw * 32 + rg * 16 + g;
                #pragma unroll
                for (int j = 0; j < 4; j++) {
                    const int m0p = 8 * j + 2 * t;
                    float4 pA = *reinterpret_cast<float4*>(smc + (bd - sb) + BO_P0 + m0p * 16);
                    float4 pB = *reinterpret_cast<float4*>(smc + (bd - sb) + BO_P0 + (m0p + 1) * 16);
                    float2 cA = *reinterpret_cast<float2*>(smc + (bd - sb) + BO_P1 + m0p * 8);
                    float2 cB = *reinterpret_cast<float2*>(smc + (bd - sb) + BO_P1 + (m0p + 1) * 8);
                    float gn[4];
                    #pragma unroll
                    for (int i = 0; i < 4; i++) {
                        float u = c1[4 * j + i];
                        float v = c1[(j + 4) * 4 + i];
                        float znv = zn[rg][i >> 1];
                        float4 pp = (i & 1) ? pB : pA;
                        float2 cc = (i & 1) ? cB : cA;
                        float tq = v - cc.x;
                        float q = fmaf(pp.x, znv, pp.y);
                        q = fmaf(pp.z, u, q);
                        q = fmaf(pp.w * tq, tq, q);
                        q = fmaxf(q, QCLAMP);
                        gn[i] = cc.y * ex2f(q);
                    }
                    __nv_bfloat16 h0 = __float2bfloat16(gn[0]), h1 = __float2bfloat16(gn[1]);
                    __nv_bfloat16 h2 = __float2bfloat16(gn[2]), h3 = __float2bfloat16(gn[3]);
                    char* r0 = smc + SM_A2Z + rowA * 144;
                    char* r1 = smc + SM_A2Z + (rowA + 8) * 144;
                    *reinterpret_cast<uint32_t*>(r0 + m0p * 2) = pk(h0, h1);
                    *reinterpret_cast<uint32_t*>(r1 + m0p * 2) = pk(h2, h3);
                    *reinterpret_cast<uint32_t*>(r0 + (32 + m0p) * 2) =
                        pk(__float2bfloat16(gn[0] - __bfloat162float(h0)),
                           __float2bfloat16(gn[1] - __bfloat162float(h1)));
                    *reinterpret_cast<uint32_t*>(r1 + (32 + m0p) * 2) =
                        pk(__float2bfloat16(gn[2] - __bfloat162float(h2)),
                           __float2bfloat16(gn[3] - __bfloat162float(h3)));
                }
            }
            __threadfence_block();
            BARA(1, 256);                      // gains(ch) ready
        }
    } else {
        // ================= CONSUMER warps 4-7: output GEMM =================
        const int ctid = tid - 128, cw = ctid >> 5;
        float acc[64];
        #pragma unroll
        for (int i = 0; i < 64; i++) acc[i] = 0.f;
        {   // initial prefetch B(0)
            const int grp = ms * NCHUNK;
            uint32_t nd = sb + SM_BUF;
            #pragma unroll
            for (int i = 0; i < 4; i++) {
                int o = ctid + i * 128, r = o >> 3, c = o & 7;
                CPA16(nd + BO_B + r * 144 + c * 16,
                      g_TB + (size_t)grp * 8192 + sh * 64 + r * 128 + c * 8);
            }
            CPCOMMIT();
        }
        for (int ch = 0; ch < NCHUNK; ch++) {
            const uint32_t bd = sb + SM_BUF + (ch & 1) * BUF_SZ;
            CPWAIT0();
            BARS(4, 128);                     // B(ch) landed; B(ch-1) reads done
            if (ch + 1 < NCHUNK) {
                const int grp = ms * NCHUNK + ch + 1;
                uint32_t nd = sb + SM_BUF + ((ch + 1) & 1) * BUF_SZ;
                #pragma unroll
                for (int i = 0; i < 4; i++) {
                    int o = ctid + i * 128, r = o >> 3, c = o & 7;
                    CPA16(nd + BO_B + r * 144 + c * 16,
                          g_TB + (size_t)grp * 8192 + sh * 64 + r * 128 + c * 8);
                }
                CPCOMMIT();
            }
            BARS(1, 256);                     // gains(ch) ready
            uint32_t af[2][4][4];
            #pragma unroll
            for (int rg = 0; rg < 2; rg++)
                #pragma unroll
                for (int kt = 0; kt < 4; kt++)
                    ldsm4(af[rg][kt], lmaddr(sb + SM_A2Z, cw * 32 + rg * 16, kt * 16, 144, mat, lr));
            BARA(2, 256);                     // gains(ch) consumed
            #pragma unroll
            for (int nt2 = 0; nt2 < 4; nt2++) {
                uint32_t bf[4][4];
                #pragma unroll
                for (int kt = 0; kt < 4; kt++)
                    ldsm4t(bf[kt], lmaddr(bd + BO_B, kt * 16, nt2 * 16, 144, mat, lr));
                #pragma unroll
                for (int rg = 0; rg < 2; rg++) {
                    float* a = acc + rg * 32 + nt2 * 8;
                    mmabf(a,     af[rg][0], bf[0][0], bf[0][1]);   // gh0*th0
                    mmabf(a + 4, af[rg][0], bf[0][2], bf[0][3]);
                    mmabf(a,     af[rg][2], bf[0][0], bf[0][1]);   // gl0*th0
                    mmabf(a + 4, af[rg][2], bf[0][2], bf[0][3]);
                    mmabf(a,     af[rg][1], bf[1][0], bf[1][1]);   // gh1*th1
                    mmabf(a + 4, af[rg][1], bf[1][2], bf[1][3]);
                    mmabf(a,     af[rg][3], bf[1][0], bf[1][1]);   // gl1*th1
                    mmabf(a + 4, af[rg][3], bf[1][2], bf[1][3]);
                    mmabf(a,     af[rg][0], bf[2][0], bf[2][1]);   // gh0*tl0
                    mmabf(a + 4, af[rg][0], bf[2][2], bf[2][3]);
                    mmabf(a,     af[rg][1], bf[3][0], bf[3][1]);   // gh1*tl1
                    mmabf(a + 4, af[rg][1], bf[3][2], bf[3][3]);
                }
            }
        }
        // write partials
        float* op = g_part + ((size_t)ms * NB + bb * 128 + cw * 32) * NS + sh * 64;
        #pragma unroll
        for (int rg = 0; rg < 2; rg++)
            #pragma unroll
            for (int nt2 = 0; nt2 < 4; nt2++)
                #pragma unroll
                for (int h = 0; h < 2; h++) {
                    const float* a = acc + rg * 32 + nt2 * 8 + h * 4;
                    int col = nt2 * 16 + h * 8 + 2 * t;
                    *reinterpret_cast<float2*>(op + (rg * 16 + g) * NS + col) =
                        make_float2(a[0], a[1]);
                    *reinterpret_cast<float2*>(op + (rg * 16 + g + 8) * NS + col) =
                        make_float2(a[2], a[3]);
                }
    }
}

__global__ void reduce_kernel(float* __restrict__ out) {
    int idx = blockIdx.x * blockDim.x + threadIdx.x;   // B*S/2 threads
    const float2* gp = reinterpret_cast<const float2*>(g_part);
    const size_t stride = (size_t)NB * NS / 2;
    float2 a0 = {0,0}, a1 = {0,0}, a2 = {0,0}, a3 = {0,0};
    #pragma unroll
    for (int p = 0; p < 4; p++) {
        float2 v0 = gp[(4 * p + 0) * stride + idx];
        float2 v1 = gp[(4 * p + 1) * stride + idx];
        float2 v2 = gp[(4 * p + 2) * stride + idx];
        float2 v3 = gp[(4 * p + 3) * stride + idx];
        a0.x += v0.x; a0.y += v0.y;  a1.x += v1.x; a1.y += v1.y;
        a2.x += v2.x; a2.y += v2.y;  a3.x += v3.x; a3.y += v3.y;
    }
    a0.x += a1.x + a2.x + a3.x;
    a0.y += a1.y + a2.y + a3.y;
    reinterpret_cast<float2*>(out)[idx] = a0;
}

extern "C" void kernel_launch(void* const* d_in, const int* in_sizes, int n_in,
                              void* d_out, int out_size) {
    const float* z     = (const float*)d_in[0];
    const float* zj    = (const float*)d_in[1];
    const float* vd    = (const float*)d_in[2];
    const float* that  = (const float*)d_in[3];
    const float* alpha = (const float*)d_in[4];
    const float* sp    = (const float*)d_in[5];
    const float* spr   = (const float*)d_in[6];
    float* out = (float*)d_out;

    prep_z_kernel<<<4, 256>>>(z);
    prep_m_kernel<<<NGRP, 256>>>(zj, vd, alpha, sp, spr, that);
    fused_kernel<<<dim3(NB / 128, MSPLIT, 2), 256>>>();
    reduce_kernel<<<512, 128>>>(out);
}